// round 7
// baseline (speedup 1.0000x reference)
#include <cuda_runtime.h>
#include <cuda_pipeline_primitives.h>
#include <cstdint>

// Problem constants (YOLO loss, S=7, P=2, C=20)
#define NCELL   49
#define BATCHN  16384
#define DCH     30
#define TOTALC  (BATCHN * NCELL)        // 802816 cells
#define CPB     98                      // cells per block-chunk = exactly 2 batches
#define NCHUNK  (TOTALC / CPB)          // 8192 chunks
#define TPB     128                     // threads per block (98 compute-active)
#define GRID1   592                     // 4 blocks/SM * 148 SMs (single wave)
#define CHUNK_FLOATS (CPB * DCH)        // 2940 floats per array per chunk
#define CHUNK_F4     (CHUNK_FLOATS / 4) // 735 float4
#define BUF_FLOATS   (2 * CHUNK_FLOATS) // out + tgt per buffer = 5880 floats

// Scratch
__device__ __align__(16) float g_P[50 * GRID1]; // partials: rows 0..48 = G[s], row 49 = C
__device__ float    g_R[50];                    // reduced result (last block writes)
__device__ unsigned g_cnt = 0;                  // block completion counter (reset each launch)
__device__ float    g_has[TOTALC];              // has, TRANSPOSED [s][b]

// img_width/img_height may arrive as int32 or float32 scalars; decide by bit pattern.
__device__ __forceinline__ float dimval(const void* p) {
    int iv = *(const int*)p;
    if (iv > 0 && iv < 1000000) return (float)iv;
    return *(const float*)p;
}

// Stage one chunk (out + tgt, 735 float4 each) with all 128 threads.
__device__ __forceinline__ void stage_chunk(float* sbuf, const float* __restrict__ outp,
                                            const float* __restrict__ tgtp,
                                            int chunk, int t)
{
    const float4* go = (const float4*)(outp + (size_t)chunk * CHUNK_FLOATS);
    const float4* gt = (const float4*)(tgtp + (size_t)chunk * CHUNK_FLOATS);
    float4* so = (float4*)sbuf;
    float4* st = (float4*)(sbuf + CHUNK_FLOATS);
    #pragma unroll
    for (int i = 0; i < 5; i++) {       // 5*128 = 640
        __pipeline_memcpy_async(&so[i * TPB + t], &go[i * TPB + t], 16);
        __pipeline_memcpy_async(&st[i * TPB + t], &gt[i * TPB + t], 16);
    }
    if (t < CHUNK_F4 - 5 * TPB) {       // remainder 95
        __pipeline_memcpy_async(&so[5 * TPB + t], &go[5 * TPB + t], 16);
        __pipeline_memcpy_async(&st[5 * TPB + t], &gt[5 * TPB + t], 16);
    }
}

__global__ __launch_bounds__(TPB)
void yolo_cell_kernel(const float* __restrict__ outp,
                      const float* __restrict__ tgtp,
                      const void* __restrict__ wp,
                      const void* __restrict__ hp)
{
    __shared__ __align__(16) float smem[2 * BUF_FLOATS];   // 47040 B, double buffer
    __shared__ float sh_red[TPB];
    __shared__ unsigned sh_last;

    const int t = threadIdx.x;

    const float W = wp ? dimval(wp) : 448.f;
    const float H = hp ? dimval(hp) : 448.f;
    const float fw = W * (1.f / 7.f);
    const float fh = H * (1.f / 7.f);

    // s is constant per thread since CPB = 2*NCELL: s = t % 49
    const int s_id = (t < NCELL) ? t : (t - NCELL);       // valid for t < 98
    const float frj = (float)(s_id / 7);                   // row index
    const float fcj = (float)(s_id % 7);                   // col index
    const int boff = (t < NCELL) ? 0 : 1;                  // batch offset within chunk

    float Gacc = 0.f;   // per-thread coefficient-of-has accumulator
    float Cacc = 0.f;   // per-thread constant-term accumulator

    // prologue: stage first chunk into buffer 0
    int chunk = blockIdx.x;
    stage_chunk(smem, outp, tgtp, chunk, t);
    __pipeline_commit();

    int buf = 0;
    for (; chunk < NCHUNK; chunk += GRID1) {
        const int next = chunk + GRID1;
        if (next < NCHUNK) stage_chunk(smem + (buf ^ 1) * BUF_FLOATS, outp, tgtp, next, t);
        __pipeline_commit();
        if (next < NCHUNK) __pipeline_wait_prior(1);
        else               __pipeline_wait_prior(0);
        __syncthreads();

        if (t < CPB) {
            const float* s_out = smem + buf * BUF_FLOATS;
            const float* s_tgt = s_out + CHUNK_FLOATS;

            const float2* so = (const float2*)(s_out + t * DCH);
            const float2* st = (const float2*)(s_tgt + t * DCH);
            float2 o01 = so[0], o23 = so[1], o45 = so[2], o67 = so[3], o89 = so[4];
            float2 t01 = st[0], t23 = st[1], t45 = st[2];

            const float tx = t01.x, ty = t01.y;
            const float tw = t23.x * W, th = t23.y * H;
            const float has = t45.x;

            // target box (reference decode, literally)
            const float tcx = (fcj + tx) * fw;
            const float tcy = (frj + ty) * fh;
            const float tx0 = tcx - tw * 0.5f, tx1 = tcx + tw * 0.5f;
            const float ty0 = tcy - th * 0.5f, ty1 = tcy + th * 0.5f;
            const float areaT = (tx1 - tx0) * (ty1 - ty0);

            float iou0, iou1;
            {   // predictor 0: x=o[0] y=o[1] w=o[3]*W h=o[4]*H
                float cx = (fcj + o01.x) * fw;
                float cy = (frj + o01.y) * fh;
                float pw = o23.y * W, ph = o45.x * H;
                float x0 = cx - pw * 0.5f, x1 = cx + pw * 0.5f;
                float y0 = cy - ph * 0.5f, y1 = cy + ph * 0.5f;
                float iw = fmaxf(fminf(x1, tx1) - fmaxf(x0, tx0), 0.f);
                float ih = fmaxf(fminf(y1, ty1) - fmaxf(y0, ty0), 0.f);
                float inter = iw * ih;
                float area = (x1 - x0) * (y1 - y0);
                iou0 = inter / (area + areaT - inter + 1e-9f);
            }
            {   // predictor 1: x=o[5] y=o[6] w=o[8]*W h=o[9]*H
                float cx = (fcj + o45.y) * fw;
                float cy = (frj + o67.x) * fh;
                float pw = o89.x * W, ph = o89.y * H;
                float x0 = cx - pw * 0.5f, x1 = cx + pw * 0.5f;
                float y0 = cy - ph * 0.5f, y1 = cy + ph * 0.5f;
                float iw = fmaxf(fminf(x1, tx1) - fmaxf(x0, tx0), 0.f);
                float ih = fmaxf(fminf(y1, ty1) - fmaxf(y0, ty0), 0.f);
                float inter = iw * ih;
                float area = (x1 - x0) * (y1 - y0);
                iou1 = inter / (area + areaT - inter + 1e-9f);
            }

            // best = P-1 - argmax([iou1, iou0]); ties -> first => iou1>=iou0 picks 1
            const float best_conf = (iou1 >= iou0) ? o89.y : o45.x;

            // coord/conf losses for predictor L = 1
            const float px = o45.y, py = o67.x;
            const float pw = o89.x * W, ph = o89.y * H;
            const float dx = tx - px, dy = ty - py;
            const float dw = sqrtf(tw) - sqrtf(pw);
            const float dh = sqrtf(th) - sqrtf(ph);
            const float ab = dx * dx + dy * dy + dw * dw + dh * dh;
            const float dc = has - o89.y;         // t_conf - p_conf (p_conf = out[9])
            const float cm = dc * dc;

            // class mse with best_conf scaling: channels 10..29 = float2 idx 5..14
            float km = 0.f;
            #pragma unroll
            for (int k = 0; k < 10; k++) {
                float2 oc = so[5 + k];
                float2 tc = st[5 + k];
                float d0 = tc.x - oc.x * best_conf;
                float d1 = tc.y - oc.y * best_conf;
                km = fmaf(d0, d0, km);
                km = fmaf(d1, d1, km);
            }

            // transposed has stash (finalize reads coalesced); L2 absorbs the scatter
            g_has[s_id * BATCHN + 2 * chunk + boff] = has;

            // register accumulation (no per-chunk atomics/shuffles)
            Gacc += fmaf(5.f, ab, 0.5f * cm);
            Cacc += fmaf(0.5f, cm, km);
        }

        buf ^= 1;
        __syncthreads();   // all readers done before this buffer is restaged
    }

    // ---- block epilogue: combine per-thread accumulators ----
    sh_red[t] = Gacc;
    __syncthreads();
    if (t < NCELL)
        g_P[t * GRID1 + blockIdx.x] = sh_red[t] + sh_red[t + NCELL];
    __syncthreads();

    sh_red[t] = Cacc;
    __syncthreads();
    if (t < 64) sh_red[t] += sh_red[t + 64];
    __syncthreads();
    if (t < 32) {
        float v = sh_red[t] + sh_red[t + 32];
        #pragma unroll
        for (int o = 16; o > 0; o >>= 1)
            v += __shfl_down_sync(0xffffffffu, v, o);
        if (t == 0) g_P[NCELL * GRID1 + blockIdx.x] = v;
    }

    // ---- last-block reduction of g_P -> g_R ----
    __threadfence();                       // release our g_P writes
    __syncthreads();
    if (t == 0) {
        unsigned old = atomicAdd(&g_cnt, 1u);
        sh_last = (old == GRID1 - 1) ? 1u : 0u;
    }
    __syncthreads();
    if (sh_last) {
        __threadfence();                   // acquire all blocks' g_P writes
        const int w = t >> 5, lane = t & 31;
        for (int row = w; row < 50; row += 4) {
            const float4* p = (const float4*)(g_P + row * GRID1);   // 148 float4
            float acc = 0.f;
            #pragma unroll
            for (int k = 0; k < 5; k++) {
                int i = lane + 32 * k;
                if (i < GRID1 / 4) {
                    float4 v = p[i];
                    acc += (v.x + v.y) + (v.z + v.w);
                }
            }
            #pragma unroll
            for (int o = 16; o > 0; o >>= 1)
                acc += __shfl_down_sync(0xffffffffu, acc, o);
            if (lane == 0) g_R[row] = acc;
        }
        __syncthreads();
        if (t == 0) g_cnt = 0;             // reset for next graph replay
    }
}

__global__ __launch_bounds__(256)
void finalize_kernel(float* __restrict__ loss)
{
    __shared__ float sR[50];
    const int t = threadIdx.x;
    if (t < 50) sR[t] = g_R[t];
    __syncthreads();

    const int b = blockIdx.x * 256 + t;
    float acc = sR[49];                    // constant term
    #pragma unroll
    for (int s = 0; s < NCELL; s++)        // fully coalesced: stride BATCHN rows
        acc = fmaf(sR[s], g_has[s * BATCHN + b], acc);
    loss[b] = acc;
}

extern "C" void kernel_launch(void* const* d_in, const int* in_sizes, int n_in,
                              void* d_out, int out_size)
{
    const float* outp = (const float*)d_in[0];
    const float* tgtp = (const float*)d_in[1];
    const void* wp = (n_in >= 3) ? d_in[2] : nullptr;
    const void* hp = (n_in >= 4) ? d_in[3] : nullptr;
    float* loss = (float*)d_out;

    yolo_cell_kernel<<<GRID1, TPB>>>(outp, tgtp, wp, hp);
    finalize_kernel<<<BATCHN / 256, 256>>>(loss);
}